// round 9
// baseline (speedup 1.0000x reference)
#include <cuda_runtime.h>
#include <cuda_bf16.h>
#include <math.h>

#define BSZ   64
#define TT    256
#define IND   64
#define HD    768
#define NB0   48          // layer0 CTAs (16 j-cols each)
#define NB1   96          // layer1 CTAs (8 j-cols each)
#define NCTAS (NB0 + NB1)
#define NTHR  512
#define STEP_WORDS 24576  // h frag buffer per step (48kt*4mt*32lane*4w = 98304 B)

// smem layout (bytes)
#define OFF_CS   110592   // L0: 2 slabs of 16640 (stride 65); L1: 4 slabs of 8448 (stride 33)
#define OFF_BIAS 144384
#define SMEM_TOT 144896

__device__ __align__(16) unsigned g_Xf[(size_t)TT * 2048];         // x bf16 A-frags
__device__ __align__(16) unsigned g_H1f[(size_t)TT * STEP_WORDS];  // h1 frags, all t
__device__ __align__(16) unsigned g_H2f[2 * STEP_WORDS];           // h2 frags, parity
__device__ __align__(16) float    g_h2pl[BSZ * HD];                // planar fp32 h2 (last)
__device__ __align__(16) float    g_fcp[BSZ * 4];                  // fc partials
__device__ unsigned long long g_bar0 = 0;   // layer0 ticket (cumulative)
__device__ unsigned long long g_bar1 = 0;   // layer1 ticket (cumulative)

// ---------------------------------------------------------------------------
__device__ __forceinline__ void group_barrier(unsigned long long* ctr, int G)
{
    __syncthreads();
    if (threadIdx.x == 0) {
        unsigned long long old;
        asm volatile("atom.add.release.gpu.u64 %0, [%1], 1;"
                     : "=l"(old) : "l"(ctr) : "memory");
        unsigned long long need = ((old + 1ULL + (unsigned long long)(G - 1))
                                   / (unsigned long long)G) * (unsigned long long)G;
        unsigned long long v;
        do {
            asm volatile("ld.acquire.gpu.u64 %0, [%1];" : "=l"(v) : "l"(ctr) : "memory");
        } while (v < need);
    }
    __syncthreads();
}

__device__ __forceinline__ float tanh_mufu(float x)
{
    float y;
    asm("tanh.approx.f32 %0, %1;" : "=f"(y) : "f"(x));
    return y;
}
__device__ __forceinline__ float sig_mufu(float x)
{
    return 0.5f * tanh_mufu(0.5f * x) + 0.5f;
}
__device__ __forceinline__ unsigned packbf(float lo, float hi)
{
    __nv_bfloat162 v = __floats2bfloat162_rn(lo, hi);
    return *reinterpret_cast<unsigned*>(&v);
}
__device__ __forceinline__ void mma16816(float* acc, uint4 a, uint2 b)
{
    asm volatile(
        "mma.sync.aligned.m16n8k16.row.col.f32.bf16.bf16.f32 "
        "{%0,%1,%2,%3}, {%4,%5,%6,%7}, {%8,%9}, {%0,%1,%2,%3};"
        : "+f"(acc[0]), "+f"(acc[1]), "+f"(acc[2]), "+f"(acc[3])
        : "r"(a.x), "r"(a.y), "r"(a.z), "r"(a.w), "r"(b.x), "r"(b.y));
}

template<int NTOT>
__device__ __forceinline__ void put_Bfrag(__nv_bfloat16* Bsh, int n, int k, float w)
{
    int kt = k >> 4, kr = k & 15, nt = n >> 3, nn = n & 7;
    int lane = nn * 4 + ((kr & 7) >> 1);
    int word = kr >> 3, half = kr & 1;
    Bsh[(((kt * NTOT + nt) * 32 + lane) * 2 + word) * 2 + half] = __float2bfloat16(w);
}

__device__ __forceinline__ uint4 loadA(const unsigned* __restrict__ src0,
                                       const unsigned* __restrict__ src1,
                                       int split, int ktg, int mt, int lane)
{
    const unsigned* base;
    int kl;
    if (ktg < split) { base = src0; kl = ktg; }
    else             { base = src1; kl = ktg - split; }
    if (base == nullptr) return make_uint4(0u, 0u, 0u, 0u);
    return __ldcg((const uint4*)base + ((kl * 4 + mt) * 32 + lane));
}

// Warp GEMM: ktg in [kt0, kt0+KT), m-rows mi*32..+31, 4 nt (32 n-cols) at ntbase.
template<int KT, int NTOT>
__device__ __forceinline__ void gemm_warp4(const unsigned* __restrict__ src0,
                                           const unsigned* __restrict__ src1,
                                           int split,
                                           const unsigned* __restrict__ Bs,
                                           float acc[2][4][4],
                                           int lane, int kt0, int mi, int ntbase)
{
    uint4 abuf[4][2];
#pragma unroll
    for (int i = 0; i < 4; i++) {
        int ktg = kt0 + i;
        abuf[i][0] = loadA(src0, src1, split, ktg, mi * 2 + 0, lane);
        abuf[i][1] = loadA(src0, src1, split, ktg, mi * 2 + 1, lane);
    }
#pragma unroll
    for (int kk = 0; kk < KT; kk++) {
        uint4 a0 = abuf[kk & 3][0];
        uint4 a1 = abuf[kk & 3][1];
        if (kk + 4 < KT) {
            int ktg = kt0 + kk + 4;
            abuf[kk & 3][0] = loadA(src0, src1, split, ktg, mi * 2 + 0, lane);
            abuf[kk & 3][1] = loadA(src0, src1, split, ktg, mi * 2 + 1, lane);
        }
        int ktg = kt0 + kk;
        const unsigned* bbase = Bs + (((ktg * NTOT + ntbase)) * 32 + lane) * 2;
#pragma unroll
        for (int nt = 0; nt < 4; nt++) {
            uint2 bb = *(const uint2*)(bbase + nt * 64);
            mma16816(acc[0][nt], a0, bb);
            mma16816(acc[1][nt], a1, bb);
        }
    }
}

// Dump partials to a slab: phase 0 assign, phase 1 add. Caller syncs.
template<int CST>
__device__ __forceinline__ void dump_slab(float acc[2][4][4], float* Cs,
                                          int lane, int mi, int colbase, bool add)
{
    const int gp = lane >> 2, tig = lane & 3;
#pragma unroll
    for (int am = 0; am < 2; am++)
#pragma unroll
        for (int nt = 0; nt < 4; nt++) {
            int row = mi * 32 + am * 16 + gp;
            int col = colbase + nt * 8 + tig * 2;
            float* c0 = Cs + row * CST + col;
            float* c1 = Cs + (row + 8) * CST + col;
            if (!add) {
                c0[0] = acc[am][nt][0];
                c0[1] = acc[am][nt][1];
                c1[0] = acc[am][nt][2];
                c1[1] = acc[am][nt][3];
            } else {
                c0[0] += acc[am][nt][0];
                c0[1] += acc[am][nt][1];
                c1[0] += acc[am][nt][2];
                c1[1] += acc[am][nt][3];
            }
        }
}

// ---------------------------------------------------------------------------
__global__ void xprep_kernel(const float* __restrict__ x)
{
    const int t = blockIdx.x;
    const int tid = threadIdx.x;
    const float inv = 1.0f / 1.5f;
    for (int idx = tid; idx < 512; idx += 256) {
        int lane = idx & 31;
        int fm = idx >> 5;
        int kt = fm >> 2, mt = fm & 3;
        int gp = lane >> 2, tig = lane & 3;
        int b0 = mt * 16 + gp, b1 = b0 + 8;
        int k0 = kt * 16 + tig * 2;
        const float* xb0 = x + ((size_t)b0 * TT + t) * IND;
        const float* xb1 = x + ((size_t)b1 * TT + t) * IND;
        uint4 v;
        v.x = packbf(xb0[k0] * inv,     xb0[k0 + 1] * inv);
        v.y = packbf(xb1[k0] * inv,     xb1[k0 + 1] * inv);
        v.z = packbf(xb0[k0 + 8] * inv, xb0[k0 + 9] * inv);
        v.w = packbf(xb1[k0 + 8] * inv, xb1[k0 + 9] * inv);
        ((uint4*)g_Xf)[t * 512 + idx] = v;
    }
}

// ---------------------------------------------------------------------------
// Fused decoupled recurrence, 512 threads (16 warps, 4/SMSP).
// CTAs 0..47   (L0): 16 j-cols, K=832; warps (ki4, mi2, ni2), KT=13.
// CTAs 48..143 (L1): 8 j-cols, K=1536; warps (ki8, mi2), KT=12.
// ---------------------------------------------------------------------------
__global__ void __launch_bounds__(NTHR, 1)
lstm_fused(const float* __restrict__ Wih0, const float* __restrict__ Whh0,
           const float* __restrict__ bih0, const float* __restrict__ bhh0,
           const float* __restrict__ Wih1, const float* __restrict__ Whh1,
           const float* __restrict__ bih1, const float* __restrict__ bhh1)
{
    extern __shared__ char smem[];
    unsigned*      Bs  = (unsigned*)smem;
    float*         bsS = (float*)(smem + OFF_BIAS);
    __nv_bfloat16* Bsh = (__nv_bfloat16*)smem;
    __shared__ unsigned long long sh_base0;

    const int tid = threadIdx.x, lane = tid & 31, wid = tid >> 5;
    const bool isB = (blockIdx.x >= NB0);

    if (isB && tid == 0) {
        unsigned long long v;
        asm volatile("ld.acquire.gpu.u64 %0, [%1];" : "=l"(v) : "l"(&g_bar0) : "memory");
        sh_base0 = v;   // pre-launch value (L0's first arrival is far away)
    }

    if (!isB) {
        // ----------------------------- LAYER 0 -----------------------------
        float* CsA = (float*)(smem + OFF_CS);            // stride 65
        float* CsB = (float*)(smem + OFF_CS + 16640);
        const int nb = blockIdx.x, j0 = nb * 16;
        const int ki = wid >> 2, mi = (wid >> 1) & 1, ni = wid & 1;

        for (int idx = tid; idx < 64 * 832; idx += NTHR) {
            int n = idx / 832, k = idx - n * 832;
            int gate = n >> 4, jj = n & 15;
            float w = (k < 64)
                ? Wih0[(size_t)(gate * 768 + j0 + jj) * 64 + k]
                : Whh0[(size_t)(gate * 768 + j0 + jj) * 768 + (k - 64)];
            put_Bfrag<8>(Bsh, n, k, w);
        }
        if (tid < 64) {
            int g = tid >> 4, jj = tid & 15;
            bsS[tid] = bih0[g * 768 + j0 + jj] + bhh0[g * 768 + j0 + jj];
        }
        __syncthreads();

        // epilogue ownership: thread -> (b, col pair jg*2, jg*2+1), jg 0..7
        const int b = tid & 63, jg = tid >> 6;
        const int gp = b & 7, hi = (b >> 3) & 1, mt = b >> 4;
        const int wlane = gp * 4 + (jg & 3);
        const int word  = hi + 2 * (jg >> 2);

        float cst[2] = {0.f, 0.f};

        for (int t = 0; t < TT; t++) {
            float acc[2][4][4];
#pragma unroll
            for (int am = 0; am < 2; am++)
#pragma unroll
                for (int nt = 0; nt < 4; nt++)
#pragma unroll
                    for (int e = 0; e < 4; e++) acc[am][nt][e] = 0.f;

            const unsigned* src0 = g_Xf + (size_t)t * 2048;
            const unsigned* src1 = (t > 0) ? g_H1f + (size_t)(t - 1) * STEP_WORDS : nullptr;
            gemm_warp4<13, 8>(src0, src1, 4, Bs, acc, lane, ki * 13, mi, ni * 4);

            float* slab = (ki < 2) ? CsA : CsB;
#pragma unroll
            for (int p = 0; p < 2; p++) {
                if ((ki & 1) == p)
                    dump_slab<65>(acc, slab, lane, mi, ni * 32, p == 1);
                __syncthreads();
            }

            float h[2];
#pragma unroll
            for (int q = 0; q < 2; q++) {
                int c = jg * 2 + q;
                float gi = bsS[c]      + CsA[b * 65 + c]      + CsB[b * 65 + c];
                float gf = bsS[16 + c] + CsA[b * 65 + 16 + c] + CsB[b * 65 + 16 + c];
                float gg = bsS[32 + c] + CsA[b * 65 + 32 + c] + CsB[b * 65 + 32 + c];
                float go = bsS[48 + c] + CsA[b * 65 + 48 + c] + CsB[b * 65 + 48 + c];
                float I = sig_mufu(gi), F = sig_mufu(gf);
                float G = tanh_mufu(gg), O = sig_mufu(go);
                cst[q] = F * cst[q] + I * G;
                h[q] = O * tanh_mufu(cst[q]);
            }
            g_H1f[((size_t)t * STEP_WORDS)
                  + ((size_t)((nb * 4 + mt) * 32 + wlane) * 4 + word)] = packbf(h[0], h[1]);

            group_barrier(&g_bar0, NB0);
        }
    } else {
        // ----------------------------- LAYER 1 -----------------------------
        float* CsS[4];
#pragma unroll
        for (int i = 0; i < 4; i++) CsS[i] = (float*)(smem + OFF_CS + i * 8448); // stride 33
        const int s = blockIdx.x - NB0;     // 0..95
        const int jb = s * 8;
        const int ktF = s >> 1, shalf = s & 1;
        const int ki = wid >> 1, mi = wid & 1;

        for (int idx = tid; idx < 32 * 1536; idx += NTHR) {
            int n = idx / 1536, k = idx - n * 1536;
            int gate = n >> 3, jj = n & 7;
            float w = (k < 768)
                ? Wih1[(size_t)(gate * 768 + jb + jj) * 768 + k]
                : Whh1[(size_t)(gate * 768 + jb + jj) * 768 + (k - 768)];
            put_Bfrag<4>(Bsh, n, k, w);
        }
        if (tid < 32) {
            int g = tid >> 3, jj = tid & 7;
            bsS[tid] = bih1[g * 768 + jb + jj] + bhh1[g * 768 + jb + jj];
        }
        __syncthreads();

        // epilogue (tid < 256): thread -> (b, col pair jp*2,+1), jp 0..3
        const int b = tid & 63, jp = (tid >> 6) & 3;
        const bool epi = (tid < 256);
        const int gp = b & 7, hi = (b >> 3) & 1, mt = b >> 4;
        const int wlane = gp * 4 + jp;
        const int word  = hi + 2 * shalf;

        float cst[2] = {0.f, 0.f};

        for (int t = 0; t < TT; t++) {
            if (tid == 0) {
                unsigned long long need = sh_base0
                    + (unsigned long long)NB0 * (unsigned long long)(t + 1);
                unsigned long long v;
                do {
                    asm volatile("ld.acquire.gpu.u64 %0, [%1];"
                                 : "=l"(v) : "l"(&g_bar0) : "memory");
                } while (v < need);
            }
            __syncthreads();

            float acc[2][4][4];
#pragma unroll
            for (int am = 0; am < 2; am++)
#pragma unroll
                for (int nt = 0; nt < 4; nt++)
#pragma unroll
                    for (int e = 0; e < 4; e++) acc[am][nt][e] = 0.f;

            const unsigned* src0 = g_H1f + (size_t)t * STEP_WORDS;
            const unsigned* src1 = (t > 0) ? g_H2f + (size_t)((t - 1) & 1) * STEP_WORDS : nullptr;
            gemm_warp4<12, 4>(src0, src1, 48, Bs, acc, lane, ki * 12, mi, 0);

            float* slab = CsS[ki >> 1];
#pragma unroll
            for (int p = 0; p < 2; p++) {
                if ((ki & 1) == p)
                    dump_slab<33>(acc, slab, lane, mi, 0, p == 1);
                __syncthreads();
            }

            if (epi) {
                float h[2];
#pragma unroll
                for (int q = 0; q < 2; q++) {
                    int c = jp * 2 + q;
                    float gi = bsS[c],      gf = bsS[8 + c];
                    float gg = bsS[16 + c], go = bsS[24 + c];
#pragma unroll
                    for (int sl = 0; sl < 4; sl++) {
                        const float* Cp = CsS[sl] + b * 33;
                        gi += Cp[c];
                        gf += Cp[8 + c];
                        gg += Cp[16 + c];
                        go += Cp[24 + c];
                    }
                    float I = sig_mufu(gi), F = sig_mufu(gf);
                    float G = tanh_mufu(gg), O = sig_mufu(go);
                    cst[q] = F * cst[q] + I * G;
                    h[q] = O * tanh_mufu(cst[q]);
                }
                g_H2f[((size_t)(t & 1) * STEP_WORDS)
                      + ((size_t)((ktF * 4 + mt) * 32 + wlane) * 4 + word)] = packbf(h[0], h[1]);
                if (t == TT - 1) {
                    float* hp = g_h2pl + (size_t)b * HD + jb + jp * 2;
                    hp[0] = h[0]; hp[1] = h[1];
                }
            }
            group_barrier(&g_bar1, NB1);
        }
    }
}

// ---------------------------------------------------------------------------
// fc head, deterministic 2-stage
// ---------------------------------------------------------------------------
__global__ void fc1_kernel(const float* __restrict__ W1, const float* __restrict__ b1,
                           const float* __restrict__ W2)
{
    const int lg = blockIdx.x;      // 0..3
    const int b  = blockIdx.y;      // 0..63
    const int tid = threadIdx.x;    // 0..63

    __shared__ float hs[HD];
#pragma unroll
    for (int i = 0; i < 12; i++)
        hs[tid + i * 64] = g_h2pl[(size_t)b * HD + tid + i * 64];
    __syncthreads();

    const int l = lg * 64 + tid;
    const float4* w1p = (const float4*)(W1 + (size_t)l * HD);
    const float4* hp4 = (const float4*)hs;

    float acc = 0.0f;
#pragma unroll 4
    for (int k4 = 0; k4 < 192; k4++) {
        float4 wv = w1p[k4];
        float4 hv = hp4[k4];
        acc += hv.x * wv.x + hv.y * wv.y + hv.z * wv.z + hv.w * wv.w;
    }
    float z = acc + b1[l];
    float p = (z / (1.0f + fabsf(z))) * W2[l];

    __shared__ float red[64];
    red[tid] = p;
    __syncthreads();
    for (int off = 32; off > 0; off >>= 1) {
        if (tid < off) red[tid] += red[tid + off];
        __syncthreads();
    }
    if (tid == 0) g_fcp[b * 4 + lg] = red[0];
}

__global__ void fc2_kernel(const float* __restrict__ b2, float* __restrict__ out)
{
    const int b = threadIdx.x;
    if (b < BSZ) {
        float sum = g_fcp[b * 4 + 0] + g_fcp[b * 4 + 1]
                  + g_fcp[b * 4 + 2] + g_fcp[b * 4 + 3];
        out[b] = (sum + b2[0]) * 70.0f;
    }
}

// ---------------------------------------------------------------------------
extern "C" void kernel_launch(void* const* d_in, const int* in_sizes, int n_in,
                              void* d_out, int out_size)
{
    const float* x    = (const float*)d_in[0];
    const float* Wih0 = (const float*)d_in[1];
    const float* Whh0 = (const float*)d_in[2];
    const float* bih0 = (const float*)d_in[3];
    const float* bhh0 = (const float*)d_in[4];
    const float* Wih1 = (const float*)d_in[5];
    const float* Whh1 = (const float*)d_in[6];
    const float* bih1 = (const float*)d_in[7];
    const float* bhh1 = (const float*)d_in[8];
    const float* W1   = (const float*)d_in[9];
    const float* b1   = (const float*)d_in[10];
    const float* W2   = (const float*)d_in[11];
    const float* b2   = (const float*)d_in[12];
    float* out = (float*)d_out;

    cudaFuncSetAttribute(lstm_fused, cudaFuncAttributeMaxDynamicSharedMemorySize, SMEM_TOT);

    xprep_kernel<<<TT, 256>>>(x);
    lstm_fused<<<NCTAS, NTHR, SMEM_TOT>>>(Wih0, Whh0, bih0, bhh0,
                                          Wih1, Whh1, bih1, bhh1);
    fc1_kernel<<<dim3(4, BSZ), 64>>>(W1, b1, W2);
    fc2_kernel<<<1, 64>>>(b2, out);
}